// round 16
// baseline (speedup 1.0000x reference)
#include <cuda_runtime.h>
#include <float.h>
#include <math.h>

#define MAXROWS 8192
#define D32     32000
#define NT1     512
#define NW1     (NT1 / 32)
#define KFULL   15              // 8000 f4 = 15*512 + 320
#define REM     320
#define NT2     128             // 4 row-warps per K2 block
#define WPB     4
#define CAPL    112             // per-lane element slots (smem)
#define FULLM   0xffffffffu

__device__ float    g_rowmax[MAXROWS];
__device__ unsigned g_mask[MAXROWS * NT1];
__device__ int      g_flag[MAXROWS];
__device__ float    g_rowloss[MAXROWS];

#define M4(v) fmaxf(fmaxf((v).x, (v).y), fmaxf((v).z, (v).w))

__device__ __forceinline__ float warpMax(float v) {
#pragma unroll
    for (int o = 16; o; o >>= 1) v = fmaxf(v, __shfl_xor_sync(FULLM, v, o));
    return v;
}
__device__ __forceinline__ float warpSumB(float v) {    // uniform, deterministic
#pragma unroll
    for (int o = 16; o; o >>= 1) v += __shfl_xor_sync(FULLM, v, o);
    return v;
}

// ============ K1 (d==32000): pure rowmax stream + exact-threshold bits ============
// Measured 79.5 us @ 85% DRAM (5x reproduced). Bit k set iff f4max > rowmax-2,
// i.e. the f4 holds an element with X > maxX-1 = tau_lo0 (superset of every probe).
__global__ __launch_bounds__(NT1, 2) void filter32k(const float* __restrict__ in) {
    int row = blockIdx.x, tid = threadIdx.x;
    int lane = tid & 31, warp = tid >> 5;
    const float4* p4 = (const float4*)(in + (size_t)row * D32);
    __shared__ float swm[NW1];

    float m4[KFULL + 1];
#pragma unroll
    for (int k = 0; k < KFULL; k++) {
        float4 v = p4[k * NT1 + tid];
        m4[k] = M4(v);
    }
    if (tid < REM) {
        float4 v = p4[KFULL * NT1 + tid];
        m4[KFULL] = M4(v);
    } else m4[KFULL] = -FLT_MAX;

    float rm = m4[0];
#pragma unroll
    for (int k = 1; k <= KFULL; k++) rm = fmaxf(rm, m4[k]);

    float wv = warpMax(rm);
    if (lane == 0) swm[warp] = wv;
    __syncthreads();
    float bmax = swm[0];
#pragma unroll
    for (int w = 1; w < NW1; w++) bmax = fmaxf(bmax, swm[w]);

    float th = bmax - 2.0f;
    unsigned hit = 0;
#pragma unroll
    for (int k = 0; k <= KFULL; k++)
        if (m4[k] > th) hit |= (1u << k);

    g_mask[row * NT1 + tid] = hit;
    if (tid == 0) g_rowmax[row] = bmax;
}

// ============ K2 (d==32000): warp-per-row, 3x 32-way parallel search ============
__global__ __launch_bounds__(NT2) void search32k(const float* __restrict__ in,
                                                 const void* __restrict__ tgt, int n) {
    extern __shared__ float pool[];            // [WPB][CAPL*32]
    int lane = threadIdx.x & 31;
    int w    = threadIdx.x >> 5;
    int row  = blockIdx.x * WPB + w;
    if (row >= n) return;                      // warp-autonomous, no barriers

    const float* xr = in + (size_t)row * D32;
    const float4* p4 = (const float4*)xr;
    float* P = pool + w * (CAPL * 32);         // element (slot s, lane l) at P[32*s + l]

    float bmax = g_rowmax[row];
    float thr  = bmax - 2.0f;                  // raw units; exact support of tau_lo0

    // ---- single-pass gather: per-lane private smem columns ----
    int c = 0;
#pragma unroll 1
    for (int j = 0; j < 16; j++) {
        unsigned m = g_mask[row * NT1 + lane + 32 * j];
        int col = lane + 32 * j;
        while (m) {
            int b = __ffs(m) - 1;
            m &= m - 1;
            float4 v = p4[b * NT1 + col];
            if (v.x > thr) { if (c < CAPL) P[32 * c + lane] = 0.5f * v.x; c++; }
            if (v.y > thr) { if (c < CAPL) P[32 * c + lane] = 0.5f * v.y; c++; }
            if (v.z > thr) { if (c < CAPL) P[32 * c + lane] = 0.5f * v.z; c++; }
            if (v.w > thr) { if (c < CAPL) P[32 * c + lane] = 0.5f * v.w; c++; }
        }
    }
    bool ovf = __any_sync(FULLM, c > CAPL);
    __syncwarp();

    float maxX    = 0.5f * bmax;
    float tau_lo0 = maxX - 1.0f;
    float tau_hi0 = maxX - 0.005590169943749474f;   // maxX - (1/32000)^0.5
    float D       = tau_hi0 - tau_lo0;

    // ---- f_lo over pool (exact support; private columns, conflict-free) ----
    float fl = 0.f;
    if (!ovf) {
        for (int s = 0; s < c; s++) {
            float t = P[32 * s + lane] - tau_lo0;
            if (t > 0.f) fl = fmaf(t, t, fl);
        }
    }
    float f_lo = warpSumB(fl) - 1.0f;

    bool bad = ovf || (f_lo < 0.f);            // f_lo<0 mathematically impossible; paranoia
    if (lane == 0) g_flag[row] = bad ? 1 : 0;
    if (bad) return;                           // K3 handles this row

    // ---- 3 passes of 32-way search: lanes 0..30 evaluate f at 31 grid points ----
    float A    = tau_lo0;
    float step = D * 0.03125f;                 // D/32
    int   idx  = 0;
#pragma unroll 1
    for (int p = 0; p < 3; p++) {
        float tau = A + (float)(lane + 1) * step;
        float f = 0.f;
#pragma unroll 1
        for (int col = 0; col < 32; col++) {
            int cnt = __shfl_sync(FULLM, c, col);
            for (int s = 0; s < cnt; s++) {
                float X = P[32 * s + col];     // warp broadcast (1 transaction)
                float t = fmaxf(X - tau, 0.f);
                f = fmaf(t, t, f);
            }
        }
        f -= 1.0f;
        // reference accept: f_m * f_lo >= 0 (f decreasing => contiguous accept prefix)
        unsigned bal = __ballot_sync(FULLM, (f * f_lo >= 0.f) && (lane < 31));
        int k = __popc(bal);
        idx = idx * 32 + k;
        A = A + (float)k * step;
        step = step * 0.03125f;
    }
    // reference's final probed tau_m is grid point (idx | 1) at resolution D/2^15
    int   m     = idx | 1;
    float tau_f = tau_lo0 + D * ((float)m * 3.0517578125e-5f);   // m / 32768

    // ---- finals at tau_f (private columns) ----
    float s3 = 0.f, px = 0.f;
    for (int s = 0; s < c; s++) {
        float X = P[32 * s + lane];
        float t = fmaxf(X - tau_f, 0.f);
        float pq = t * t;
        s3 = fmaf(pq, t, s3);
        px = fmaf(pq, X, px);
    }
    float S3 = warpSumB(s3);
    float PX = warpSumB(px);

    // ---- target (lane-parallel dtype sniff) + loss ----
    {
        const int* t32 = (const int*)tgt;
        int lim = (n < 32) ? n : 32;
        int z = 1;
        if (lane < lim) z = (t32[2 * lane + 1] == 0);
        bool is64 = __all_sync(FULLM, z != 0);
        if (lane == 0) {
            long long v = is64 ? ((const long long*)tgt)[row] : (long long)t32[row];
            int t = (int)v;
            if (t < 0 || t >= D32) t = 0;
            float xt = __ldg(xr + t);
            // loss = (1-S3)/(alpha*(alpha-1)) + sum(p*input) - input[target]
            //      = (1-S3)/0.75 + 2*PX - xt          (input = 2*X)
            g_rowloss[row] = (1.0f - S3) / 0.75f + 2.0f * PX - xt;
        }
    }
}

// ============ block-parallel reference core (slow rows + generic d) ============
__device__ __forceinline__ float blockSumAllG(float v, float* sbuf) {
    int lane = threadIdx.x & 31, warp = threadIdx.x >> 5;
#pragma unroll
    for (int o = 16; o; o >>= 1) v += __shfl_xor_sync(FULLM, v, o);
    __syncthreads();
    if (lane == 0) sbuf[warp] = v;
    __syncthreads();
    float s = 0.f;
#pragma unroll
    for (int w = 0; w < 8; w++) s += sbuf[w];
    return s;
}

__device__ void ref_row(const float* xr, const void* tgt, int d, int n, int row,
                        float* sred) {
    float m = -FLT_MAX;
    for (int i = threadIdx.x; i < d; i += 256) m = fmaxf(m, xr[i]);
    m = warpMax(m);
    __syncthreads();
    if ((threadIdx.x & 31) == 0) sred[threadIdx.x >> 5] = m;
    __syncthreads();
    float bmax = sred[0];
#pragma unroll
    for (int w = 1; w < 8; w++) bmax = fmaxf(bmax, sred[w]);
    float maxX = 0.5f * bmax;
    float tl = maxX - 1.0f;
    float th0 = maxX - (float)(1.0 / sqrt((double)d));
    float s = 0.f;
    for (int i = threadIdx.x; i < d; i += 256) {
        float q = fmaxf(fmaf(0.5f, __ldg(xr + i), -tl), 0.f);
        s = fmaf(q, q, s);
    }
    float f_lo = blockSumAllG(s, sred) - 1.0f;
    float dm = th0 - tl, tm = tl;
#pragma unroll 1
    for (int it = 0; it < 15; it++) {
        dm *= 0.5f;
        tm = tl + dm;
        float q2 = 0.f;
        for (int i = threadIdx.x; i < d; i += 256) {
            float q = fmaxf(fmaf(0.5f, __ldg(xr + i), -tm), 0.f);
            q2 = fmaf(q, q, q2);
        }
        float fm = blockSumAllG(q2, sred) - 1.0f;
        tl = (fm * f_lo >= 0.f) ? tm : tl;
    }
    float s3 = 0.f, px = 0.f;
    for (int i = threadIdx.x; i < d; i += 256) {
        float X = 0.5f * __ldg(xr + i);
        float q = fmaxf(X - tm, 0.f);
        float p = q * q;
        s3 = fmaf(p, q, s3);
        px = fmaf(p, X, px);
    }
    float S3 = blockSumAllG(s3, sred);
    float PX = blockSumAllG(px, sred);
    if (threadIdx.x == 0) {
        const int* t32 = (const int*)tgt;
        int lim = (n < 32) ? n : 32;
        bool is64 = true;
        for (int i = 0; i < lim; i++) is64 = is64 && (t32[2 * i + 1] == 0);
        long long v = is64 ? ((const long long*)tgt)[row] : (long long)t32[row];
        int t = (int)v;
        if (t < 0 || t >= d) t = 0;
        g_rowloss[row] = (1.0f - S3) / 0.75f + 2.0f * PX - __ldg(xr + t);
    }
}

// K3: flagged rows only; everyone else exits immediately (measured +~3us idle).
__global__ __launch_bounds__(256) void flagged32k(const float* __restrict__ in,
                                                  const void* __restrict__ tgt, int n) {
    int row = blockIdx.x;
    if (!g_flag[row]) return;
    __shared__ float sred[8];
    ref_row(in + (size_t)row * D32, tgt, D32, n, row, sred);
}

// generic fallback (any d)
__global__ __launch_bounds__(256) void tsallis_gen(const float* __restrict__ in,
                                                   const void* __restrict__ tgt,
                                                   int d, int n) {
    int row = blockIdx.x;
    __shared__ float sred[8];
    ref_row(in + (size_t)row * d, tgt, d, n, row, sred);
}

// mean over rows
__global__ __launch_bounds__(1024) void reduce_kernel(float* __restrict__ out, int n) {
    __shared__ float sbuf[32];
    float s = 0.f;
    for (int i = threadIdx.x; i < n; i += 1024) s += g_rowloss[i];
#pragma unroll
    for (int o = 16; o; o >>= 1) s += __shfl_down_sync(FULLM, s, o);
    if ((threadIdx.x & 31) == 0) sbuf[threadIdx.x >> 5] = s;
    __syncthreads();
    if (threadIdx.x < 32) {
        float x = sbuf[threadIdx.x];
#pragma unroll
        for (int o = 16; o; o >>= 1) x += __shfl_down_sync(FULLM, x, o);
        if (threadIdx.x == 0) out[0] = x / (float)n;
    }
}

extern "C" void kernel_launch(void* const* d_in, const int* in_sizes, int n_in,
                              void* d_out, int out_size) {
    int idx_in = 0, idx_tg = 1;
    if (n_in >= 2 && in_sizes[1] > in_sizes[0]) { idx_in = 1; idx_tg = 0; }
    const float* in  = (const float*)d_in[idx_in];
    const void*  tgt = d_in[idx_tg];

    int n = in_sizes[idx_tg];
    if (n <= 0) n = 1;
    int d = in_sizes[idx_in] / n;
    if (n > MAXROWS) n = MAXROWS;

    if (d == D32) {
        int dyn = WPB * CAPL * 32 * (int)sizeof(float);   // 57344 B
        cudaFuncSetAttribute(search32k, cudaFuncAttributeMaxDynamicSharedMemorySize, dyn);
        filter32k<<<n, NT1>>>(in);
        search32k<<<(n + WPB - 1) / WPB, NT2, dyn>>>(in, tgt, n);
        flagged32k<<<n, 256>>>(in, tgt, n);
    } else {
        tsallis_gen<<<n, 256>>>(in, tgt, d, n);
    }
    reduce_kernel<<<1, 1024>>>((float*)d_out, n);
}

// round 17
// speedup vs baseline: 1.8017x; 1.8017x over previous
#include <cuda_runtime.h>
#include <float.h>
#include <math.h>

#define MAXROWS 8192
#define D32     32000
#define NT1     512
#define NW1     (NT1 / 32)
#define KFULL   15              // 8000 f4 = 15*512 + 320
#define REM     320
#define NT2     128             // 4 row-warps per K2 block
#define WPB     4
#define CAPL    112             // per-lane element slots (smem); worst-row lambda=67
#define FULLM   0xffffffffu

__device__ float    g_rowmax[MAXROWS];
__device__ unsigned g_mask[MAXROWS * NT1];
__device__ int      g_flag[MAXROWS];
__device__ float    g_rowloss[MAXROWS];

#define M4(v) fmaxf(fmaxf((v).x, (v).y), fmaxf((v).z, (v).w))

__device__ __forceinline__ float warpMax(float v) {
#pragma unroll
    for (int o = 16; o; o >>= 1) v = fmaxf(v, __shfl_xor_sync(FULLM, v, o));
    return v;
}
__device__ __forceinline__ float warpSumB(float v) {    // uniform, deterministic
#pragma unroll
    for (int o = 16; o; o >>= 1) v += __shfl_xor_sync(FULLM, v, o);
    return v;
}

// ============ K1 (d==32000): pure rowmax stream + exact-threshold bits ============
// Measured 79.5 us @ 85% DRAM (6x reproduced). Bit k set iff f4max > rowmax-2,
// i.e. the f4 holds an element with X > maxX-1 = tau_lo0 (superset of every probe).
__global__ __launch_bounds__(NT1, 2) void filter32k(const float* __restrict__ in) {
    int row = blockIdx.x, tid = threadIdx.x;
    int lane = tid & 31, warp = tid >> 5;
    const float4* p4 = (const float4*)(in + (size_t)row * D32);
    __shared__ float swm[NW1];

    float m4[KFULL + 1];
#pragma unroll
    for (int k = 0; k < KFULL; k++) {
        float4 v = p4[k * NT1 + tid];
        m4[k] = M4(v);
    }
    if (tid < REM) {
        float4 v = p4[KFULL * NT1 + tid];
        m4[KFULL] = M4(v);
    } else m4[KFULL] = -FLT_MAX;

    float rm = m4[0];
#pragma unroll
    for (int k = 1; k <= KFULL; k++) rm = fmaxf(rm, m4[k]);

    float wv = warpMax(rm);
    if (lane == 0) swm[warp] = wv;
    __syncthreads();
    float bmax = swm[0];
#pragma unroll
    for (int w = 1; w < NW1; w++) bmax = fmaxf(bmax, swm[w]);

    float th = bmax - 2.0f;
    unsigned hit = 0;
#pragma unroll
    for (int k = 0; k <= KFULL; k++)
        if (m4[k] > th) hit |= (1u << k);

    g_mask[row * NT1 + tid] = hit;
    if (tid == 0) g_rowmax[row] = bmax;
}

// ============ K2 (d==32000): warp-per-row; smem elements; serial warp bisection ============
__global__ __launch_bounds__(NT2) void bisect32k(const float* __restrict__ in,
                                                 const void* __restrict__ tgt, int n) {
    extern __shared__ float pool[];            // [WPB][CAPL*32]
    int lane = threadIdx.x & 31;
    int w    = threadIdx.x >> 5;
    int row  = blockIdx.x * WPB + w;
    if (row >= n) return;                      // warp-autonomous, zero barriers

    const float* xr = in + (size_t)row * D32;
    const float4* p4 = (const float4*)xr;
    float* P = pool + w * (CAPL * 32);         // element (slot s, lane l) at P[32*s + l]

    float bmax = g_rowmax[row];
    float thr  = bmax - 2.0f;                  // raw units; exact support of tau_lo0

    // ---- single-pass gather: per-lane private smem columns (R16-proven) ----
    int c = 0;
#pragma unroll 1
    for (int j = 0; j < 16; j++) {
        unsigned m = g_mask[row * NT1 + lane + 32 * j];
        int col = lane + 32 * j;
        while (m) {
            int b = __ffs(m) - 1;
            m &= m - 1;
            float4 v = p4[b * NT1 + col];
            if (v.x > thr) { if (c < CAPL) P[32 * c + lane] = 0.5f * v.x; c++; }
            if (v.y > thr) { if (c < CAPL) P[32 * c + lane] = 0.5f * v.y; c++; }
            if (v.z > thr) { if (c < CAPL) P[32 * c + lane] = 0.5f * v.z; c++; }
            if (v.w > thr) { if (c < CAPL) P[32 * c + lane] = 0.5f * v.w; c++; }
        }
    }
    bool ovf = __any_sync(FULLM, c > CAPL);
    if (lane == 0) g_flag[row] = ovf ? 1 : 0;
    if (ovf) return;                           // K3 handles this row (block-parallel)
    __syncwarp();

    float maxX    = 0.5f * bmax;
    float tau_lo0 = maxX - 1.0f;
    float tau_hi0 = maxX - 0.005590169943749474f;   // maxX - (1/32000)^0.5

    // ---- f_lo over pool (exact: excluded elements contribute 0 at tau >= tau_lo0) ----
    float fl = 0.f;
    for (int s = 0; s < c; s++) {
        float t = P[32 * s + lane] - tau_lo0;
        if (t > 0.f) fl = fmaf(t, t, fl);
    }
    float f_lo = warpSumB(fl) - 1.0f;

    // ---- 15 serial bisection iterations, smem-resident, shuffle-reduced ----
    float tau_lo = tau_lo0;
    float dm     = tau_hi0 - tau_lo0;
    float tau_m  = tau_lo0;
#pragma unroll 1
    for (int it = 0; it < 15; it++) {
        dm *= 0.5f;
        tau_m = tau_lo + dm;
        float s = 0.f;
        for (int j = 0; j < c; j++) {
            float t = fmaxf(P[32 * j + lane] - tau_m, 0.f);
            s = fmaf(t, t, s);
        }
        float fm = warpSumB(s) - 1.0f;
        tau_lo = (fm * f_lo >= 0.f) ? tau_m : tau_lo;   // uniform across warp
    }

    // ---- finals at last tau_m ----
    float s3 = 0.f, px = 0.f;
    for (int j = 0; j < c; j++) {
        float X = P[32 * j + lane];
        float t = fmaxf(X - tau_m, 0.f);
        float p = t * t;
        s3 = fmaf(p, t, s3);
        px = fmaf(p, X, px);
    }
    float S3 = warpSumB(s3);
    float PX = warpSumB(px);

    // ---- target (lane-parallel dtype sniff) + loss ----
    {
        const int* t32 = (const int*)tgt;
        int lim = (n < 32) ? n : 32;
        int z = 1;
        if (lane < lim) z = (t32[2 * lane + 1] == 0);
        bool is64 = __all_sync(FULLM, z != 0);
        if (lane == 0) {
            long long v = is64 ? ((const long long*)tgt)[row] : (long long)t32[row];
            int t = (int)v;
            if (t < 0 || t >= D32) t = 0;
            float xt = __ldg(xr + t);
            // loss = (1-S3)/(alpha*(alpha-1)) + sum(p*input) - input[target]
            //      = (1-S3)/0.75 + 2*PX - xt          (input = 2*X)
            g_rowloss[row] = (1.0f - S3) / 0.75f + 2.0f * PX - xt;
        }
    }
}

// ============ block-parallel reference core (overflow rows + generic d) ============
__device__ __forceinline__ float blockSumAllG(float v, float* sbuf) {
    int lane = threadIdx.x & 31, warp = threadIdx.x >> 5;
#pragma unroll
    for (int o = 16; o; o >>= 1) v += __shfl_xor_sync(FULLM, v, o);
    __syncthreads();
    if (lane == 0) sbuf[warp] = v;
    __syncthreads();
    float s = 0.f;
#pragma unroll
    for (int w = 0; w < 8; w++) s += sbuf[w];
    return s;
}

__device__ void ref_row(const float* xr, const void* tgt, int d, int n, int row,
                        float* sred) {
    float m = -FLT_MAX;
    for (int i = threadIdx.x; i < d; i += 256) m = fmaxf(m, xr[i]);
    m = warpMax(m);
    __syncthreads();
    if ((threadIdx.x & 31) == 0) sred[threadIdx.x >> 5] = m;
    __syncthreads();
    float bmax = sred[0];
#pragma unroll
    for (int w = 1; w < 8; w++) bmax = fmaxf(bmax, sred[w]);
    float maxX = 0.5f * bmax;
    float tl = maxX - 1.0f;
    float th0 = maxX - (float)(1.0 / sqrt((double)d));
    float s = 0.f;
    for (int i = threadIdx.x; i < d; i += 256) {
        float q = fmaxf(fmaf(0.5f, __ldg(xr + i), -tl), 0.f);
        s = fmaf(q, q, s);
    }
    float f_lo = blockSumAllG(s, sred) - 1.0f;
    float dm = th0 - tl, tm = tl;
#pragma unroll 1
    for (int it = 0; it < 15; it++) {
        dm *= 0.5f;
        tm = tl + dm;
        float q2 = 0.f;
        for (int i = threadIdx.x; i < d; i += 256) {
            float q = fmaxf(fmaf(0.5f, __ldg(xr + i), -tm), 0.f);
            q2 = fmaf(q, q, q2);
        }
        float fm = blockSumAllG(q2, sred) - 1.0f;
        tl = (fm * f_lo >= 0.f) ? tm : tl;
    }
    float s3 = 0.f, px = 0.f;
    for (int i = threadIdx.x; i < d; i += 256) {
        float X = 0.5f * __ldg(xr + i);
        float q = fmaxf(X - tm, 0.f);
        float p = q * q;
        s3 = fmaf(p, q, s3);
        px = fmaf(p, X, px);
    }
    float S3 = blockSumAllG(s3, sred);
    float PX = blockSumAllG(px, sred);
    if (threadIdx.x == 0) {
        const int* t32 = (const int*)tgt;
        int lim = (n < 32) ? n : 32;
        bool is64 = true;
        for (int i = 0; i < lim; i++) is64 = is64 && (t32[2 * i + 1] == 0);
        long long v = is64 ? ((const long long*)tgt)[row] : (long long)t32[row];
        int t = (int)v;
        if (t < 0 || t >= d) t = 0;
        g_rowloss[row] = (1.0f - S3) / 0.75f + 2.0f * PX - __ldg(xr + t);
    }
}

// K3: flagged rows only; others exit immediately (measured ~3us when idle).
__global__ __launch_bounds__(256) void flagged32k(const float* __restrict__ in,
                                                  const void* __restrict__ tgt, int n) {
    int row = blockIdx.x;
    if (!g_flag[row]) return;
    __shared__ float sred[8];
    ref_row(in + (size_t)row * D32, tgt, D32, n, row, sred);
}

// generic fallback (any d)
__global__ __launch_bounds__(256) void tsallis_gen(const float* __restrict__ in,
                                                   const void* __restrict__ tgt,
                                                   int d, int n) {
    int row = blockIdx.x;
    __shared__ float sred[8];
    ref_row(in + (size_t)row * d, tgt, d, n, row, sred);
}

// mean over rows
__global__ __launch_bounds__(1024) void reduce_kernel(float* __restrict__ out, int n) {
    __shared__ float sbuf[32];
    float s = 0.f;
    for (int i = threadIdx.x; i < n; i += 1024) s += g_rowloss[i];
#pragma unroll
    for (int o = 16; o; o >>= 1) s += __shfl_down_sync(FULLM, s, o);
    if ((threadIdx.x & 31) == 0) sbuf[threadIdx.x >> 5] = s;
    __syncthreads();
    if (threadIdx.x < 32) {
        float x = sbuf[threadIdx.x];
#pragma unroll
        for (int o = 16; o; o >>= 1) x += __shfl_down_sync(FULLM, x, o);
        if (threadIdx.x == 0) out[0] = x / (float)n;
    }
}

extern "C" void kernel_launch(void* const* d_in, const int* in_sizes, int n_in,
                              void* d_out, int out_size) {
    int idx_in = 0, idx_tg = 1;
    if (n_in >= 2 && in_sizes[1] > in_sizes[0]) { idx_in = 1; idx_tg = 0; }
    const float* in  = (const float*)d_in[idx_in];
    const void*  tgt = d_in[idx_tg];

    int n = in_sizes[idx_tg];
    if (n <= 0) n = 1;
    int d = in_sizes[idx_in] / n;
    if (n > MAXROWS) n = MAXROWS;

    if (d == D32) {
        int dyn = WPB * CAPL * 32 * (int)sizeof(float);   // 57344 B
        cudaFuncSetAttribute(bisect32k, cudaFuncAttributeMaxDynamicSharedMemorySize, dyn);
        filter32k<<<n, NT1>>>(in);
        bisect32k<<<(n + WPB - 1) / WPB, NT2, dyn>>>(in, tgt, n);
        flagged32k<<<n, 256>>>(in, tgt, n);
    } else {
        tsallis_gen<<<n, 256>>>(in, tgt, d, n);
    }
    reduce_kernel<<<1, 1024>>>((float*)d_out, n);
}